// round 10
// baseline (speedup 1.0000x reference)
#include <cuda_runtime.h>
#include <cuda_bf16.h>
#include <cstdint>

#define H_FEATS 128
#define D2 256
#define LN_EPS 1e-5f
#define MAX_NODES 262144

// Node table: x=sum(h), y=sum(h^2), z=dot(h, gW[0:128]), w=dot(h, gW[128:256])
__device__ float4 g_node_tab[MAX_NODES];
__device__ float  g_Sgw;      // sum(gamma*W)
__device__ float  g_C;        // sum(beta*W) + b
__device__ int    g_arrive;   // barrier arrival counter (releaser resets to 0)
__device__ int    g_phase;    // barrier sense (alternates across runs; any init ok)

// ---------------------------------------------------------------------------
// Persistent fused kernel. Grid sized by host for full co-residency, so the
// software grid barrier cannot deadlock.
// Phase 1 (node): grid-stride, 64 nodes/block-iter (8 lanes/node, 2 nodes per
//   lane-group => 8 float4 loads in flight). Also L2-prefetch src/dst.
// Barrier (sense-reversing, self-resetting).
// Phase 2 (edge): grid-stride, 4 edges/thread-iter, 8 table gathers in flight.
// ---------------------------------------------------------------------------
__global__ void __launch_bounds__(256) fused_kernel(
        const float* __restrict__ h,
        const int*   __restrict__ src,
        const int*   __restrict__ dst,
        const float* __restrict__ gamma,
        const float* __restrict__ beta,
        const float* __restrict__ W,
        const float* __restrict__ b,
        float*       __restrict__ out,
        int n_nodes, int n_edges) {
    int t = threadIdx.x;

    // Read barrier sense BEFORE any arrival can flip it.
    int my_phase = *(volatile int*)&g_phase;

    // ---------------- prologue: gW to smem, scalars (block 0) --------------
    __shared__ float4 sgW[64];   // gW as 64 float4s
    {
        float w  = W[t];
        float gw = gamma[t] * w;
        reinterpret_cast<float*>(sgW)[t] = gw;

        if (blockIdx.x == 0) {
            __shared__ float sA[D2];
            __shared__ float sB[D2];
            sA[t] = gw;
            sB[t] = beta[t] * w;
            __syncthreads();
            #pragma unroll
            for (int off = 128; off > 0; off >>= 1) {
                if (t < off) { sA[t] += sA[t + off]; sB[t] += sB[t + off]; }
                __syncthreads();
            }
            if (t == 0) {
                g_Sgw = sA[0];
                g_C   = sB[0] + __ldg(b);
            }
        } else {
            __syncthreads();
        }
    }

    // ---------------- L2 prefetch of edge indices (overlaps node DRAM) ----
    {
        int gid = blockIdx.x * 256 + t;
        long src_bytes = (long)n_edges * 4;
        long off = (long)gid * 128;
        if (off < src_bytes) {
            asm volatile("prefetch.global.L2 [%0];" ::
                         "l"((const char*)src + off));
            asm volatile("prefetch.global.L2 [%0];" ::
                         "l"((const char*)dst + off));
        }
    }

    // ------------------------- NODE PHASE (grid-stride) -------------------
    int group = t >> 3;           // lane-group (0..31), handles 2 nodes/iter
    int sub   = t & 7;            // lane within group (0..7)
    int n_node_iters = (n_nodes + 63) >> 6;   // 64 nodes per block-iter

    float4 gl0 = sgW[sub];       float4 gh0 = sgW[32 + sub];
    float4 gl1 = sgW[sub + 8];   float4 gh1 = sgW[40 + sub];
    float4 gl2 = sgW[sub + 16];  float4 gh2 = sgW[48 + sub];
    float4 gl3 = sgW[sub + 24];  float4 gh3 = sgW[56 + sub];

    for (int nb = blockIdx.x; nb < n_node_iters; nb += gridDim.x) {
        int node0 = nb * 64 + group * 2;
        int node1 = node0 + 1;
        if (node0 >= n_nodes) continue;
        bool has1 = node1 < n_nodes;

        const float4* r0 = reinterpret_cast<const float4*>(h + (size_t)node0 * H_FEATS);
        const float4* r1 = reinterpret_cast<const float4*>(h + (size_t)node1 * H_FEATS);

        // 8 independent 16B loads in flight
        float4 a0 = __ldg(r0 + sub);
        float4 a1 = __ldg(r0 + sub + 8);
        float4 a2 = __ldg(r0 + sub + 16);
        float4 a3 = __ldg(r0 + sub + 24);
        float4 b0, b1, b2, b3;
        if (has1) {
            b0 = __ldg(r1 + sub);
            b1 = __ldg(r1 + sub + 8);
            b2 = __ldg(r1 + sub + 16);
            b3 = __ldg(r1 + sub + 24);
        } else {
            b0 = b1 = b2 = b3 = make_float4(0.f, 0.f, 0.f, 0.f);
        }

        // node0 partials
        float s1a = (a0.x + a0.y + a0.z + a0.w) + (a1.x + a1.y + a1.z + a1.w)
                  + (a2.x + a2.y + a2.z + a2.w) + (a3.x + a3.y + a3.z + a3.w);
        float s2a = a0.x*a0.x + a0.y*a0.y + a0.z*a0.z + a0.w*a0.w
                  + a1.x*a1.x + a1.y*a1.y + a1.z*a1.z + a1.w*a1.w
                  + a2.x*a2.x + a2.y*a2.y + a2.z*a2.z + a2.w*a2.w
                  + a3.x*a3.x + a3.y*a3.y + a3.z*a3.z + a3.w*a3.w;
        float dsa = a0.x*gl0.x + a0.y*gl0.y + a0.z*gl0.z + a0.w*gl0.w
                  + a1.x*gl1.x + a1.y*gl1.y + a1.z*gl1.z + a1.w*gl1.w
                  + a2.x*gl2.x + a2.y*gl2.y + a2.z*gl2.z + a2.w*gl2.w
                  + a3.x*gl3.x + a3.y*gl3.y + a3.z*gl3.z + a3.w*gl3.w;
        float dda = a0.x*gh0.x + a0.y*gh0.y + a0.z*gh0.z + a0.w*gh0.w
                  + a1.x*gh1.x + a1.y*gh1.y + a1.z*gh1.z + a1.w*gh1.w
                  + a2.x*gh2.x + a2.y*gh2.y + a2.z*gh2.z + a2.w*gh2.w
                  + a3.x*gh3.x + a3.y*gh3.y + a3.z*gh3.z + a3.w*gh3.w;
        // node1 partials
        float s1b = (b0.x + b0.y + b0.z + b0.w) + (b1.x + b1.y + b1.z + b1.w)
                  + (b2.x + b2.y + b2.z + b2.w) + (b3.x + b3.y + b3.z + b3.w);
        float s2b = b0.x*b0.x + b0.y*b0.y + b0.z*b0.z + b0.w*b0.w
                  + b1.x*b1.x + b1.y*b1.y + b1.z*b1.z + b1.w*b1.w
                  + b2.x*b2.x + b2.y*b2.y + b2.z*b2.z + b2.w*b2.w
                  + b3.x*b3.x + b3.y*b3.y + b3.z*b3.z + b3.w*b3.w;
        float dsb = b0.x*gl0.x + b0.y*gl0.y + b0.z*gl0.z + b0.w*gl0.w
                  + b1.x*gl1.x + b1.y*gl1.y + b1.z*gl1.z + b1.w*gl1.w
                  + b2.x*gl2.x + b2.y*gl2.y + b2.z*gl2.z + b2.w*gl2.w
                  + b3.x*gl3.x + b3.y*gl3.y + b3.z*gl3.z + b3.w*gl3.w;
        float ddb = b0.x*gh0.x + b0.y*gh0.y + b0.z*gh0.z + b0.w*gh0.w
                  + b1.x*gh1.x + b1.y*gh1.y + b1.z*gh1.z + b1.w*gh1.w
                  + b2.x*gh2.x + b2.y*gh2.y + b2.z*gh2.z + b2.w*gh2.w
                  + b3.x*gh3.x + b3.y*gh3.y + b3.z*gh3.z + b3.w*gh3.w;

        #pragma unroll
        for (int off = 4; off > 0; off >>= 1) {
            s1a += __shfl_down_sync(0xFFFFFFFFu, s1a, off);
            s2a += __shfl_down_sync(0xFFFFFFFFu, s2a, off);
            dsa += __shfl_down_sync(0xFFFFFFFFu, dsa, off);
            dda += __shfl_down_sync(0xFFFFFFFFu, dda, off);
            s1b += __shfl_down_sync(0xFFFFFFFFu, s1b, off);
            s2b += __shfl_down_sync(0xFFFFFFFFu, s2b, off);
            dsb += __shfl_down_sync(0xFFFFFFFFu, dsb, off);
            ddb += __shfl_down_sync(0xFFFFFFFFu, ddb, off);
        }
        if (sub == 0) {
            g_node_tab[node0] = make_float4(s1a, s2a, dsa, dda);
            if (has1) g_node_tab[node1] = make_float4(s1b, s2b, dsb, ddb);
        }
    }

    // ------------------- GRID BARRIER (sense-reversing) --------------------
    __syncthreads();
    if (t == 0) {
        __threadfence();                               // publish table stores
        int ticket = atomicAdd(&g_arrive, 1);
        if (ticket == (int)gridDim.x - 1) {
            g_arrive = 0;                              // reset for next run
            __threadfence();
            atomicExch(&g_phase, my_phase ^ 1);        // release
        } else {
            while (*(volatile int*)&g_phase == my_phase) {
                __nanosleep(32);
            }
        }
        __threadfence();                               // acquire
    }
    __syncthreads();

    // ------------------------- EDGE PHASE (grid-stride) --------------------
    const float Sgw = g_Sgw;
    const float C   = g_C;
    const float inv = 1.0f / (float)D2;

    const int4* src4 = reinterpret_cast<const int4*>(src);
    const int4* dst4 = reinterpret_cast<const int4*>(dst);
    float4* out4 = reinterpret_cast<float4*>(out);

    int nquads = n_edges >> 2;
    int gid    = blockIdx.x * blockDim.x + t;
    int stride = gridDim.x * blockDim.x;

    for (int q = gid; q < nquads; q += stride) {
        int4 s4 = __ldg(src4 + q);
        int4 d4 = __ldg(dst4 + q);

        float4 a0 = __ldg(&g_node_tab[s4.x]);
        float4 c0 = __ldg(&g_node_tab[d4.x]);
        float4 a1 = __ldg(&g_node_tab[s4.y]);
        float4 c1 = __ldg(&g_node_tab[d4.y]);
        float4 a2 = __ldg(&g_node_tab[s4.z]);
        float4 c2 = __ldg(&g_node_tab[d4.z]);
        float4 a3 = __ldg(&g_node_tab[s4.w]);
        float4 c3 = __ldg(&g_node_tab[d4.w]);

        float4 r;
        {
            float mu  = (a0.x + c0.x) * inv;
            float var = fmaf(-mu, mu, (a0.y + c0.y) * inv);
            r.x = fmaf(rsqrtf(var + LN_EPS), fmaf(-mu, Sgw, a0.z + c0.w), C);
        }
        {
            float mu  = (a1.x + c1.x) * inv;
            float var = fmaf(-mu, mu, (a1.y + c1.y) * inv);
            r.y = fmaf(rsqrtf(var + LN_EPS), fmaf(-mu, Sgw, a1.z + c1.w), C);
        }
        {
            float mu  = (a2.x + c2.x) * inv;
            float var = fmaf(-mu, mu, (a2.y + c2.y) * inv);
            r.z = fmaf(rsqrtf(var + LN_EPS), fmaf(-mu, Sgw, a2.z + c2.w), C);
        }
        {
            float mu  = (a3.x + c3.x) * inv;
            float var = fmaf(-mu, mu, (a3.y + c3.y) * inv);
            r.w = fmaf(rsqrtf(var + LN_EPS), fmaf(-mu, Sgw, a3.z + c3.w), C);
        }
        out4[q] = r;
    }

    // tail edges (n_edges % 4): first threads of block 0
    if (blockIdx.x == 0) {
        int i = (nquads << 2) + t;
        if (i < n_edges) {
            float4 a = __ldg(&g_node_tab[src[i]]);
            float4 c = __ldg(&g_node_tab[dst[i]]);
            float mu  = (a.x + c.x) * inv;
            float var = fmaf(-mu, mu, (a.y + c.y) * inv);
            out[i] = fmaf(rsqrtf(var + LN_EPS), fmaf(-mu, Sgw, a.z + c.w), C);
        }
    }
}

// ---------------------------------------------------------------------------
// Launch
// Inputs: 0=h [N*128] f32, 1=src [E] i32, 2=dst [E] i32,
//         3=ln_gamma [256] f32, 4=ln_beta [256] f32, 5=W [256] f32, 6=b [1] f32
// Output: [E] f32
// ---------------------------------------------------------------------------
extern "C" void kernel_launch(void* const* d_in, const int* in_sizes, int n_in,
                              void* d_out, int out_size) {
    const float* h     = (const float*)d_in[0];
    const int*   src   = (const int*)d_in[1];
    const int*   dst   = (const int*)d_in[2];
    const float* gamma = (const float*)d_in[3];
    const float* beta  = (const float*)d_in[4];
    const float* W     = (const float*)d_in[5];
    const float* b     = (const float*)d_in[6];
    float* out = (float*)d_out;

    int n_nodes = in_sizes[0] / H_FEATS;
    int n_edges = in_sizes[1];

    // Grid sized for guaranteed full co-residency -> barrier is deadlock-free.
    int dev = 0, sms = 148, occ = 0;
    cudaGetDevice(&dev);
    cudaDeviceGetAttribute(&sms, cudaDevAttrMultiProcessorCount, dev);
    cudaOccupancyMaxActiveBlocksPerMultiprocessor(&occ, fused_kernel, 256, 0);
    if (occ < 1) occ = 1;
    int grid = sms * occ;

    fused_kernel<<<grid, 256>>>(h, src, dst, gamma, beta, W, b, out,
                                n_nodes, n_edges);
}